// round 8
// baseline (speedup 1.0000x reference)
#include <cuda_runtime.h>
#include <cuda_bf16.h>
#include <math.h>
#include <stdint.h>

#define BATCH 4
#define SEQ   2048
#define DM    1024
#define NH    16
#define HD    64
#define MROWS (BATCH*SEQ)      // 8192
#define NBH   (BATCH*NH)       // 64

// Q pre-scale folded into projection: log2(e) / sqrt(D_MODEL)
#define QSCALE 0.04508422002598762f   // 1.4426950408889634 / 32

// ---------------- scratch (device globals: allocation-free rule) -------------
__device__ __nv_bfloat16 g_xhi[(size_t)MROWS * DM];
__device__ __nv_bfloat16 g_xlo[(size_t)MROWS * DM];
__device__ __nv_bfloat16 g_chi[(size_t)MROWS * DM];     // ctx split
__device__ __nv_bfloat16 g_clo[(size_t)MROWS * DM];
__device__ __nv_bfloat16 g_wThi[(size_t)4 * DM * DM];   // W^T [n][k]
__device__ __nv_bfloat16 g_wTlo[(size_t)4 * DM * DM];
__device__ __nv_bfloat16 g_qhi[(size_t)NBH * SEQ * HD]; // [bh][s][64]
__device__ __nv_bfloat16 g_qlo[(size_t)NBH * SEQ * HD];
__device__ __nv_bfloat16 g_khi[(size_t)NBH * SEQ * HD];
__device__ __nv_bfloat16 g_klo[(size_t)NBH * SEQ * HD];
__device__ __nv_bfloat16 g_vhi[(size_t)NBH * SEQ * HD];
__device__ __nv_bfloat16 g_vlo[(size_t)NBH * SEQ * HD];

// ======================= asm helpers =========================================
__device__ __forceinline__ void ldm_x4(uint32_t addr, uint32_t* r) {
    asm volatile("ldmatrix.sync.aligned.m8n8.x4.shared.b16 {%0,%1,%2,%3}, [%4];"
                 : "=r"(r[0]), "=r"(r[1]), "=r"(r[2]), "=r"(r[3]) : "r"(addr));
}
__device__ __forceinline__ void ldm_x4_t(uint32_t addr, uint32_t* r) {
    asm volatile("ldmatrix.sync.aligned.m8n8.x4.trans.shared.b16 {%0,%1,%2,%3}, [%4];"
                 : "=r"(r[0]), "=r"(r[1]), "=r"(r[2]), "=r"(r[3]) : "r"(addr));
}
__device__ __forceinline__ void mma_bf16(float* c, const uint32_t* a,
                                         uint32_t b0, uint32_t b1) {
    asm volatile(
        "mma.sync.aligned.m16n8k16.row.col.f32.bf16.bf16.f32 "
        "{%0,%1,%2,%3}, {%4,%5,%6,%7}, {%8,%9}, {%0,%1,%2,%3};"
        : "+f"(c[0]), "+f"(c[1]), "+f"(c[2]), "+f"(c[3])
        : "r"(a[0]), "r"(a[1]), "r"(a[2]), "r"(a[3]), "r"(b0), "r"(b1));
}
__device__ __forceinline__ uint32_t pkbf(float x, float y) {
    __nv_bfloat162 t = __floats2bfloat162_rn(x, y);
    return *(uint32_t*)&t;
}
// round-to-nearest-even bf16 value, returned as fp32 (pure ALU, no F2F)
__device__ __forceinline__ float rbf(float x) {
    uint32_t u = __float_as_uint(x);
    u = (u + 0x7FFFu + ((u >> 16) & 1u)) & 0xFFFF0000u;
    return __uint_as_float(u);
}
__device__ __forceinline__ void cp16(uint32_t dst, const void* src) {
    asm volatile("cp.async.cg.shared.global [%0], [%1], 16;"
                 :: "r"(dst), "l"(src) : "memory");
}
#define CP_COMMIT() asm volatile("cp.async.commit_group;" ::: "memory")
#define CP_WAIT1()  asm volatile("cp.async.wait_group 1;" ::: "memory")
#define CP_WAIT0()  asm volatile("cp.async.wait_group 0;" ::: "memory")

// =============================================================================
// split fp32 x -> hi/lo bf16
// =============================================================================
__global__ __launch_bounds__(256) void k_split(const float* __restrict__ x)
{
    const size_t i = ((size_t)blockIdx.x * 256 + threadIdx.x) * 4;
    float4 v = *(const float4*)(x + i);
    float vv[4] = {v.x, v.y, v.z, v.w};
    __nv_bfloat16 h[4], l[4];
#pragma unroll
    for (int u = 0; u < 4; u++) {
        h[u] = __float2bfloat16(vv[u]);
        l[u] = __float2bfloat16(vv[u] - __bfloat162float(h[u]));
    }
    *(uint2*)(g_xhi + i) = *(uint2*)h;
    *(uint2*)(g_xlo + i) = *(uint2*)l;
}

// =============================================================================
// transpose + split weights: W [k][n] fp32 -> WT hi/lo [n][k] bf16
// =============================================================================
__global__ __launch_bounds__(256) void k_wT(
    const float* __restrict__ Wq, const float* __restrict__ Wk,
    const float* __restrict__ Wv, const float* __restrict__ Wo)
{
    const int z = blockIdx.z;
    const float* __restrict__ W = (z == 0) ? Wq : (z == 1) ? Wk : (z == 2) ? Wv : Wo;
    __nv_bfloat16* __restrict__ Th = g_wThi + (size_t)z * DM * DM;
    __nv_bfloat16* __restrict__ Tl = g_wTlo + (size_t)z * DM * DM;

    __shared__ float t[32][33];
    const int bk = blockIdx.y * 32, bn = blockIdx.x * 32;
    const int tx = threadIdx.x & 31, ty = threadIdx.x >> 5;

#pragma unroll
    for (int i = 0; i < 4; i++)
        t[ty + i * 8][tx] = W[(size_t)(bk + ty + i * 8) * DM + bn + tx];
    __syncthreads();
#pragma unroll
    for (int i = 0; i < 4; i++) {
        const float v = t[tx][ty + i * 8];
        const __nv_bfloat16 h = __float2bfloat16(v);
        const size_t o = (size_t)(bn + ty + i * 8) * DM + bk + tx;
        Th[o] = h;
        Tl[o] = __float2bfloat16(v - __bfloat162float(h));
    }
}

// =============================================================================
// mma.sync bf16-split GEMM, 128x128 block, BK=32, cp.async 2-stage pipeline.
// mode 0 (Q): output pre-scaled by QSCALE (folds attention scale + log2e).
// =============================================================================
#define PITCH 40
#define GSTG  (4 * 128 * PITCH)                  // elems per stage = 20480
#define GEMM_SMEM_BYTES (2 * GSTG * 2)           // 81920

__global__ __launch_bounds__(256, 2) void k_gemm(
    const float* __restrict__ b0p, const float* __restrict__ b1p,
    const float* __restrict__ b2p, float* __restrict__ finalOut, int modeBase)
{
    extern __shared__ __nv_bfloat16 smg[];
    const uint32_t aBase = (uint32_t)__cvta_generic_to_shared(smg);

    const int z = blockIdx.z;
    const int mode = modeBase + z;
    const __nv_bfloat16* __restrict__ Ahi = (mode < 3) ? g_xhi : g_chi;
    const __nv_bfloat16* __restrict__ Alo = (mode < 3) ? g_xlo : g_clo;
    const int wsel = (mode < 3) ? z : 3;
    const __nv_bfloat16* __restrict__ Bhi = g_wThi + (size_t)wsel * DM * DM;
    const __nv_bfloat16* __restrict__ Blo = g_wTlo + (size_t)wsel * DM * DM;
    const float* __restrict__ bias = (mode == 0) ? b0p : (mode == 1) ? b1p
                                    : (mode == 2) ? b2p : b0p;
    const float oscale = (mode == 0) ? QSCALE : 1.0f;

    const int bm = blockIdx.y * 128;
    const int bn = blockIdx.x * 128;
    const int tid = threadIdx.x;
    const int wid = tid >> 5;
    const int lane = tid & 31;
    const int wy = wid >> 1;
    const int wx = wid & 1;

    const uint32_t lmo = (uint32_t)((lane & 15) * PITCH + (lane >> 4) * 8);

    const int lr  = tid >> 2;            // 0..63 -> rows lr, lr+64 via it
    const int lsg = (tid & 3) * 8;       // elem offset in row

    float acc[2][8][4];
#pragma unroll
    for (int a = 0; a < 2; a++)
#pragma unroll
        for (int b = 0; b < 8; b++)
#pragma unroll
            for (int c = 0; c < 4; c++) acc[a][b][c] = 0.f;

    auto issue = [&](int kc, int stg) {
        const int k0 = kc * 32;
        const uint32_t sb = aBase + (uint32_t)(stg * GSTG) * 2;
#pragma unroll
        for (int it = 0; it < 2; it++) {
            const int r = lr + it * 64;
            const size_t gA = (size_t)(bm + r) * DM + k0 + lsg;
            const size_t gB = (size_t)(bn + r) * DM + k0 + lsg;
            const uint32_t so = (uint32_t)(r * PITCH + lsg) * 2;
            cp16(sb + so,                    Ahi + gA);
            cp16(sb + 5120 * 2 + so,         Alo + gA);
            cp16(sb + 10240 * 2 + so,        Bhi + gB);
            cp16(sb + 15360 * 2 + so,        Blo + gB);
        }
    };

    issue(0, 0);
    CP_COMMIT();

    for (int kc = 0; kc < 32; kc++) {
        const int cur = kc & 1;
        if (kc + 1 < 32) {
            issue(kc + 1, (kc + 1) & 1);
            CP_COMMIT();
            CP_WAIT1();
        } else {
            CP_WAIT0();
        }
        __syncthreads();

        const uint32_t sb = aBase + (uint32_t)(cur * GSTG) * 2;
        const uint32_t aAhi = sb;
        const uint32_t aAlo = sb + 5120 * 2;
        const uint32_t aBhi = sb + 10240 * 2;
        const uint32_t aBlo = sb + 15360 * 2;

#pragma unroll
        for (int ks = 0; ks < 2; ks++) {
            uint32_t ahi[2][4], alo[2][4], bhi[4][4], blo[4][4];
#pragma unroll
            for (int mt = 0; mt < 2; mt++) {
                const uint32_t org = (uint32_t)((wy * 32 + mt * 16) * PITCH + ks * 16);
                ldm_x4(aAhi + (org + lmo) * 2, ahi[mt]);
                ldm_x4(aAlo + (org + lmo) * 2, alo[mt]);
            }
#pragma unroll
            for (int np = 0; np < 4; np++) {
                const uint32_t org = (uint32_t)((wx * 64 + np * 16) * PITCH + ks * 16);
                ldm_x4(aBhi + (org + lmo) * 2, bhi[np]);
                ldm_x4(aBlo + (org + lmo) * 2, blo[np]);
            }
#pragma unroll
            for (int mt = 0; mt < 2; mt++) {
#pragma unroll
                for (int np = 0; np < 4; np++) {
                    mma_bf16(acc[mt][np * 2 + 0], ahi[mt], bhi[np][0], bhi[np][2]);
                    mma_bf16(acc[mt][np * 2 + 1], ahi[mt], bhi[np][1], bhi[np][3]);
                    mma_bf16(acc[mt][np * 2 + 0], alo[mt], bhi[np][0], bhi[np][2]);
                    mma_bf16(acc[mt][np * 2 + 1], alo[mt], bhi[np][1], bhi[np][3]);
                    mma_bf16(acc[mt][np * 2 + 0], ahi[mt], blo[np][0], blo[np][2]);
                    mma_bf16(acc[mt][np * 2 + 1], ahi[mt], blo[np][1], blo[np][3]);
                }
            }
        }
        __syncthreads();
    }

    // epilogue
    const int g   = lane >> 2;
    const int tig = lane & 3;
#pragma unroll
    for (int mt = 0; mt < 2; mt++) {
        const int row0 = bm + wy * 32 + mt * 16 + g;
#pragma unroll
        for (int nf = 0; nf < 8; nf++) {
            const int col = bn + wx * 64 + nf * 8 + tig * 2;
            const float* ac = acc[mt][nf];
            const float bx = bias[col], by = bias[col + 1];
            if (mode < 3) {
                __nv_bfloat16* __restrict__ ohi = (mode == 0) ? g_qhi : (mode == 1) ? g_khi : g_vhi;
                __nv_bfloat16* __restrict__ olo = (mode == 0) ? g_qlo : (mode == 1) ? g_klo : g_vlo;
                const int h = col >> 6, dh = col & 63;
#pragma unroll
                for (int rr = 0; rr < 2; rr++) {
                    const int row = row0 + rr * 8;
                    const int b = row >> 11, s = row & 2047;
                    const float vx = (ac[rr * 2 + 0] + bx) * oscale;
                    const float vy = (ac[rr * 2 + 1] + by) * oscale;
                    const size_t o = (((size_t)(b * NH + h)) * SEQ + s) * HD + dh;
                    *(uint32_t*)&ohi[o] = pkbf(vx, vy);
                    *(uint32_t*)&olo[o] = pkbf(vx - rbf(vx), vy - rbf(vy));
                }
            } else {
#pragma unroll
                for (int rr = 0; rr < 2; rr++) {
                    const int row = row0 + rr * 8;
                    float2 v = make_float2(ac[rr * 2 + 0] + bx, ac[rr * 2 + 1] + by);
                    *(float2*)&finalOut[(size_t)row * DM + col] = v;
                }
            }
        }
    }
}

// =============================================================================
// Flash attention, split bf16, Q-tile 128 x KV-tile 64, cp.async pipeline.
// No running max (scores provably small); exp2-domain; deferred l-reduction.
// =============================================================================
#define APITCH 72
#define AQ_ELEMS (128 * APITCH)          // 9216
#define ASTG     (4 * 64 * APITCH)       // 18432 elems per KV stage
#define ATT_SMEM_BYTES ((2 * AQ_ELEMS + 2 * ASTG) * 2)   // 110592

__global__ __launch_bounds__(256) void k_attn()
{
    extern __shared__ __nv_bfloat16 smb[];
    const uint32_t aBase = (uint32_t)__cvta_generic_to_shared(smb);
    const uint32_t aQhi = aBase;
    const uint32_t aQlo = aBase + AQ_ELEMS * 2;

    const int bh  = blockIdx.y;
    const int qt  = (int)gridDim.x - 1 - (int)blockIdx.x;  // heavy first
    const int tid = threadIdx.x;
    const int wid = tid >> 5;
    const int lane = tid & 31;
    const int g   = lane >> 2;
    const int q2  = lane & 3;

    const __nv_bfloat16* __restrict__ Qhi = g_qhi + (size_t)bh * SEQ * HD;
    const __nv_bfloat16* __restrict__ Qlo = g_qlo + (size_t)bh * SEQ * HD;
    const __nv_bfloat16* __restrict__ Khi = g_khi + (size_t)bh * SEQ * HD;
    const __nv_bfloat16* __restrict__ Klo = g_klo + (size_t)bh * SEQ * HD;
    const __nv_bfloat16* __restrict__ Vhi = g_vhi + (size_t)bh * SEQ * HD;
    const __nv_bfloat16* __restrict__ Vlo = g_vlo + (size_t)bh * SEQ * HD;

    // load Q tile (128 x 64) via cp.async
#pragma unroll
    for (int it = 0; it < 4; it++) {
        const int idx = it * 256 + tid;
        const int r  = idx >> 3;
        const int c8 = (idx & 7) * 8;
        const size_t gsrc = (size_t)(qt * 128 + r) * HD + c8;
        const uint32_t so = (uint32_t)(r * APITCH + c8) * 2;
        cp16(aQhi + so, Qhi + gsrc);
        cp16(aQlo + so, Qlo + gsrc);
    }

    const uint32_t lmo = (uint32_t)((lane & 15) * APITCH + (lane >> 4) * 8);
    const int lr  = tid >> 3;            // 0..31 (rows lr, lr+32)
    const int lc8 = (tid & 7) * 8;

    auto issueKV = [&](int kb, int stg) {
        const uint32_t sb = aBase + (uint32_t)(2 * AQ_ELEMS + stg * ASTG) * 2;
#pragma unroll
        for (int it = 0; it < 2; it++) {
            const int r = lr + it * 32;
            const size_t gsrc = (size_t)(kb * 64 + r) * HD + lc8;
            const uint32_t so = (uint32_t)(r * APITCH + lc8) * 2;
            cp16(sb + so,                      Khi + gsrc);
            cp16(sb + (64 * APITCH) * 2 + so,  Klo + gsrc);
            cp16(sb + (128 * APITCH) * 2 + so, Vhi + gsrc);
            cp16(sb + (192 * APITCH) * 2 + so, Vlo + gsrc);
        }
    };

    issueKV(0, 0);
    CP_COMMIT();

    float o[8][4];
#pragma unroll
    for (int j = 0; j < 8; j++)
#pragma unroll
        for (int c = 0; c < 4; c++) o[j][c] = 0.f;
    float l0 = 0.f, l1 = 0.f;   // per-thread partial sums (reduced at end)

    const int row0 = qt * 128 + wid * 16 + g;
    const int row1 = row0 + 8;
    const int wrow_max = qt * 128 + wid * 16 + 15;   // warp's max Q row
    const int nkb = 2 * qt + 2;

    for (int kb = 0; kb < nkb; kb++) {
        if (kb + 1 < nkb) {
            issueKV(kb + 1, (kb + 1) & 1);
            CP_COMMIT();
            CP_WAIT1();
        } else {
            CP_WAIT0();
        }
        __syncthreads();

        // fully-masked warp-block: no contribution (p would be all zero)
        if (kb * 64 > wrow_max) { __syncthreads(); continue; }

        const uint32_t sb = aBase + (uint32_t)(2 * AQ_ELEMS + (kb & 1) * ASTG) * 2;
        const uint32_t aKhi = sb;
        const uint32_t aKlo = sb + (64 * APITCH) * 2;
        const uint32_t aVhi = sb + (128 * APITCH) * 2;
        const uint32_t aVlo = sb + (192 * APITCH) * 2;

        // ---- S' = Q' K^T (3-pass split); Q' pre-scaled by log2e/32 ----
        float sf[8][4];
#pragma unroll
        for (int j = 0; j < 8; j++)
#pragma unroll
            for (int c = 0; c < 4; c++) sf[j][c] = 0.f;

#pragma unroll
        for (int kc = 0; kc < 4; kc++) {
            uint32_t qh[4], ql[4];
            const uint32_t orgA = (uint32_t)((wid * 16) * APITCH + kc * 16);
            ldm_x4(aQhi + (orgA + lmo) * 2, qh);
            ldm_x4(aQlo + (orgA + lmo) * 2, ql);
#pragma unroll
            for (int np = 0; np < 4; np++) {
                uint32_t kh[4], kl[4];
                const uint32_t orgB = (uint32_t)((np * 16) * APITCH + kc * 16);
                ldm_x4(aKhi + (orgB + lmo) * 2, kh);
                ldm_x4(aKlo + (orgB + lmo) * 2, kl);
                mma_bf16(sf[np * 2 + 0], qh, kh[0], kh[2]);
                mma_bf16(sf[np * 2 + 1], qh, kh[1], kh[3]);
                mma_bf16(sf[np * 2 + 0], ql, kh[0], kh[2]);
                mma_bf16(sf[np * 2 + 1], ql, kh[1], kh[3]);
                mma_bf16(sf[np * 2 + 0], qh, kl[0], kl[2]);
                mma_bf16(sf[np * 2 + 1], qh, kl[1], kl[3]);
            }
        }

        // ---- mask + exp2 + partial sums (no running max needed) ----
        float sum0 = 0.f, sum1 = 0.f;
#pragma unroll
        for (int j = 0; j < 8; j++) {
            const int col = kb * 64 + j * 8 + q2 * 2;
            sf[j][0] = (col     > row0) ? 0.f : exp2f(sf[j][0]);
            sf[j][1] = (col + 1 > row0) ? 0.f : exp2f(sf[j][1]);
            sf[j][2] = (col     > row1) ? 0.f : exp2f(sf[j][2]);
            sf[j][3] = (col + 1 > row1) ? 0.f : exp2f(sf[j][3]);
            sum0 += sf[j][0] + sf[j][1];
            sum1 += sf[j][2] + sf[j][3];
        }
        l0 += sum0;
        l1 += sum1;

        // pack P -> split bf16 A fragments (ALU bit-trick for lo)
        uint32_t pah[4][4], pal[4][4];
#pragma unroll
        for (int kc = 0; kc < 4; kc++) {
            const int j0 = kc * 2, j1 = kc * 2 + 1;
            float f0 = sf[j0][0], f1 = sf[j0][1], f2 = sf[j0][2], f3 = sf[j0][3];
            float g0 = sf[j1][0], g1 = sf[j1][1], g2 = sf[j1][2], g3 = sf[j1][3];
            pah[kc][0] = pkbf(f0, f1);
            pah[kc][1] = pkbf(f2, f3);
            pah[kc][2] = pkbf(g0, g1);
            pah[kc][3] = pkbf(g2, g3);
            pal[kc][0] = pkbf(f0 - rbf(f0), f1 - rbf(f1));
            pal[kc][1] = pkbf(f2 - rbf(f2), f3 - rbf(f3));
            pal[kc][2] = pkbf(g0 - rbf(g0), g1 - rbf(g1));
            pal[kc][3] = pkbf(g2 - rbf(g2), g3 - rbf(g3));
        }

        // ---- O += P V (3-pass split) ----
#pragma unroll
        for (int kc = 0; kc < 4; kc++) {
#pragma unroll
            for (int np = 0; np < 4; np++) {
                uint32_t vh[4], vl[4];
                const uint32_t org = (uint32_t)((kc * 16) * APITCH + np * 16);
                ldm_x4_t(aVhi + (org + lmo) * 2, vh);
                ldm_x4_t(aVlo + (org + lmo) * 2, vl);
                mma_bf16(o[np * 2 + 0], pah[kc], vh[0], vh[1]);
                mma_bf16(o[np * 2 + 1], pah[kc], vh[2], vh[3]);
                mma_bf16(o[np * 2 + 0], pal[kc], vh[0], vh[1]);
                mma_bf16(o[np * 2 + 1], pal[kc], vh[2], vh[3]);
                mma_bf16(o[np * 2 + 0], pah[kc], vl[0], vl[1]);
                mma_bf16(o[np * 2 + 1], pah[kc], vl[2], vl[3]);
            }
        }
        __syncthreads();   // all reads of stage done before refill
    }

    // ---- deferred l reduction across the quad (2 shfl total) ----
    l0 += __shfl_xor_sync(0xffffffff, l0, 1);
    l0 += __shfl_xor_sync(0xffffffff, l0, 2);
    l1 += __shfl_xor_sync(0xffffffff, l1, 1);
    l1 += __shfl_xor_sync(0xffffffff, l1, 2);

    // ---- epilogue: normalize + write ctx split bf16 ----
    const float inv0 = 1.0f / l0;
    const float inv1 = 1.0f / l1;
    const int b = bh >> 4, h = bh & 15;
    const int s0 = qt * 128 + wid * 16 + g;
#pragma unroll
    for (int j = 0; j < 8; j++) {
        const int d = j * 8 + q2 * 2;
        {
            const float vx = o[j][0] * inv0, vy = o[j][1] * inv0;
            const size_t off = ((size_t)(b * SEQ + s0)) * DM + h * HD + d;
            *(uint32_t*)&g_chi[off] = pkbf(vx, vy);
            *(uint32_t*)&g_clo[off] = pkbf(vx - rbf(vx), vy - rbf(vy));
        }
        {
            const float vx = o[j][2] * inv1, vy = o[j][3] * inv1;
            const size_t off = ((size_t)(b * SEQ + s0 + 8)) * DM + h * HD + d;
            *(uint32_t*)&g_chi[off] = pkbf(vx, vy);
            *(uint32_t*)&g_clo[off] = pkbf(vx - rbf(vx), vy - rbf(vy));
        }
    }
}

// =============================================================================
extern "C" void kernel_launch(void* const* d_in, const int* in_sizes, int n_in,
                              void* d_out, int out_size)
{
    (void)in_sizes; (void)n_in; (void)out_size;
    const float* x  = (const float*)d_in[0];
    const float* Wq = (const float*)d_in[1];
    const float* bq = (const float*)d_in[2];
    const float* Wk = (const float*)d_in[3];
    const float* bk = (const float*)d_in[4];
    const float* Wv = (const float*)d_in[5];
    const float* bv = (const float*)d_in[6];
    const float* Wo = (const float*)d_in[7];
    const float* bo = (const float*)d_in[8];
    float* out = (float*)d_out;

    cudaFuncSetAttribute(k_gemm, cudaFuncAttributeMaxDynamicSharedMemorySize,
                         GEMM_SMEM_BYTES);
    cudaFuncSetAttribute(k_attn, cudaFuncAttributeMaxDynamicSharedMemorySize,
                         ATT_SMEM_BYTES);

    // 1) weight transpose + split, input split
    k_wT<<<dim3(32, 32, 4), 256>>>(Wq, Wk, Wv, Wo);
    k_split<<<(MROWS * DM) / 1024, 256>>>(x);

    // 2) QKV projections (mma.sync + cp.async pipeline); Q pre-scaled
    k_gemm<<<dim3(DM / 128, MROWS / 128, 3), 256, GEMM_SMEM_BYTES>>>(bq, bk, bv, nullptr, 0);

    // 3) flash attention (no-max softmax, exp2 domain)
    k_attn<<<dim3(SEQ / 128, NBH), 256, ATT_SMEM_BYTES>>>();

    // 4) output projection
    k_gemm<<<dim3(DM / 128, MROWS / 128, 1), 256, GEMM_SMEM_BYTES>>>(bo, bo, bo, out, 3);
}

// round 9
// speedup vs baseline: 1.0312x; 1.0312x over previous
#include <cuda_runtime.h>
#include <cuda_bf16.h>
#include <math.h>
#include <stdint.h>

#define BATCH 4
#define SEQ   2048
#define DM    1024
#define NH    16
#define HD    64
#define MROWS (BATCH*SEQ)      // 8192
#define NBH   (BATCH*NH)       // 64

// Q pre-scale folded into projection: log2(e) / sqrt(D_MODEL)
#define QSCALE 0.04508422002598762f   // 1.4426950408889634 / 32

// ---------------- scratch (device globals: allocation-free rule) -------------
__device__ __nv_bfloat16 g_xhi[(size_t)MROWS * DM];
__device__ __nv_bfloat16 g_xlo[(size_t)MROWS * DM];
__device__ __nv_bfloat16 g_chi[(size_t)MROWS * DM];     // ctx split
__device__ __nv_bfloat16 g_clo[(size_t)MROWS * DM];
__device__ __nv_bfloat16 g_wThi[(size_t)4 * DM * DM];   // W^T [n][k]
__device__ __nv_bfloat16 g_wTlo[(size_t)4 * DM * DM];
__device__ __nv_bfloat16 g_qhi[(size_t)NBH * SEQ * HD]; // [bh][s][64]
__device__ __nv_bfloat16 g_qlo[(size_t)NBH * SEQ * HD];
__device__ __nv_bfloat16 g_khi[(size_t)NBH * SEQ * HD];
__device__ __nv_bfloat16 g_klo[(size_t)NBH * SEQ * HD];
__device__ __nv_bfloat16 g_vhi[(size_t)NBH * SEQ * HD];
__device__ __nv_bfloat16 g_vlo[(size_t)NBH * SEQ * HD];

// ======================= asm helpers =========================================
__device__ __forceinline__ void ldm_x4(uint32_t addr, uint32_t* r) {
    asm volatile("ldmatrix.sync.aligned.m8n8.x4.shared.b16 {%0,%1,%2,%3}, [%4];"
                 : "=r"(r[0]), "=r"(r[1]), "=r"(r[2]), "=r"(r[3]) : "r"(addr));
}
__device__ __forceinline__ void ldm_x4_t(uint32_t addr, uint32_t* r) {
    asm volatile("ldmatrix.sync.aligned.m8n8.x4.trans.shared.b16 {%0,%1,%2,%3}, [%4];"
                 : "=r"(r[0]), "=r"(r[1]), "=r"(r[2]), "=r"(r[3]) : "r"(addr));
}
__device__ __forceinline__ void mma_bf16(float* c, const uint32_t* a,
                                         uint32_t b0, uint32_t b1) {
    asm volatile(
        "mma.sync.aligned.m16n8k16.row.col.f32.bf16.bf16.f32 "
        "{%0,%1,%2,%3}, {%4,%5,%6,%7}, {%8,%9}, {%0,%1,%2,%3};"
        : "+f"(c[0]), "+f"(c[1]), "+f"(c[2]), "+f"(c[3])
        : "r"(a[0]), "r"(a[1]), "r"(a[2]), "r"(a[3]), "r"(b0), "r"(b1));
}
__device__ __forceinline__ uint32_t pkbf(float x, float y) {
    __nv_bfloat162 t = __floats2bfloat162_rn(x, y);
    return *(uint32_t*)&t;
}
// round-to-nearest-even bf16 value, returned as fp32 (pure ALU, no F2F)
__device__ __forceinline__ float rbf(float x) {
    uint32_t u = __float_as_uint(x);
    u = (u + 0x7FFFu + ((u >> 16) & 1u)) & 0xFFFF0000u;
    return __uint_as_float(u);
}
// single-MUFU exp2 (independent of fast-math flags)
__device__ __forceinline__ float ex2(float x) {
    float y;
    asm("ex2.approx.f32 %0, %1;" : "=f"(y) : "f"(x));
    return y;
}
__device__ __forceinline__ void cp16(uint32_t dst, const void* src) {
    asm volatile("cp.async.cg.shared.global [%0], [%1], 16;"
                 :: "r"(dst), "l"(src) : "memory");
}
#define CP_COMMIT() asm volatile("cp.async.commit_group;" ::: "memory")
#define CP_WAIT1()  asm volatile("cp.async.wait_group 1;" ::: "memory")
#define CP_WAIT0()  asm volatile("cp.async.wait_group 0;" ::: "memory")

// =============================================================================
// split fp32 x -> hi/lo bf16
// =============================================================================
__global__ __launch_bounds__(256) void k_split(const float* __restrict__ x)
{
    const size_t i = ((size_t)blockIdx.x * 256 + threadIdx.x) * 4;
    float4 v = *(const float4*)(x + i);
    float vv[4] = {v.x, v.y, v.z, v.w};
    __nv_bfloat16 h[4], l[4];
#pragma unroll
    for (int u = 0; u < 4; u++) {
        h[u] = __float2bfloat16(vv[u]);
        l[u] = __float2bfloat16(vv[u] - __bfloat162float(h[u]));
    }
    *(uint2*)(g_xhi + i) = *(uint2*)h;
    *(uint2*)(g_xlo + i) = *(uint2*)l;
}

// =============================================================================
// transpose + split weights: W [k][n] fp32 -> WT hi/lo [n][k] bf16
// =============================================================================
__global__ __launch_bounds__(256) void k_wT(
    const float* __restrict__ Wq, const float* __restrict__ Wk,
    const float* __restrict__ Wv, const float* __restrict__ Wo)
{
    const int z = blockIdx.z;
    const float* __restrict__ W = (z == 0) ? Wq : (z == 1) ? Wk : (z == 2) ? Wv : Wo;
    __nv_bfloat16* __restrict__ Th = g_wThi + (size_t)z * DM * DM;
    __nv_bfloat16* __restrict__ Tl = g_wTlo + (size_t)z * DM * DM;

    __shared__ float t[32][33];
    const int bk = blockIdx.y * 32, bn = blockIdx.x * 32;
    const int tx = threadIdx.x & 31, ty = threadIdx.x >> 5;

#pragma unroll
    for (int i = 0; i < 4; i++)
        t[ty + i * 8][tx] = W[(size_t)(bk + ty + i * 8) * DM + bn + tx];
    __syncthreads();
#pragma unroll
    for (int i = 0; i < 4; i++) {
        const float v = t[tx][ty + i * 8];
        const __nv_bfloat16 h = __float2bfloat16(v);
        const size_t o = (size_t)(bn + ty + i * 8) * DM + bk + tx;
        Th[o] = h;
        Tl[o] = __float2bfloat16(v - __bfloat162float(h));
    }
}

// =============================================================================
// mma.sync bf16-split GEMM, 128x128 block, BK=32, cp.async 2-stage pipeline.
// mode 0 (Q): output pre-scaled by QSCALE (folds attention scale + log2e).
// =============================================================================
#define PITCH 40
#define GSTG  (4 * 128 * PITCH)                  // elems per stage = 20480
#define GEMM_SMEM_BYTES (2 * GSTG * 2)           // 81920

__global__ __launch_bounds__(256, 2) void k_gemm(
    const float* __restrict__ b0p, const float* __restrict__ b1p,
    const float* __restrict__ b2p, float* __restrict__ finalOut, int modeBase)
{
    extern __shared__ __nv_bfloat16 smg[];
    const uint32_t aBase = (uint32_t)__cvta_generic_to_shared(smg);

    const int z = blockIdx.z;
    const int mode = modeBase + z;
    const __nv_bfloat16* __restrict__ Ahi = (mode < 3) ? g_xhi : g_chi;
    const __nv_bfloat16* __restrict__ Alo = (mode < 3) ? g_xlo : g_clo;
    const int wsel = (mode < 3) ? z : 3;
    const __nv_bfloat16* __restrict__ Bhi = g_wThi + (size_t)wsel * DM * DM;
    const __nv_bfloat16* __restrict__ Blo = g_wTlo + (size_t)wsel * DM * DM;
    const float* __restrict__ bias = (mode == 0) ? b0p : (mode == 1) ? b1p
                                    : (mode == 2) ? b2p : b0p;
    const float oscale = (mode == 0) ? QSCALE : 1.0f;

    const int bm = blockIdx.y * 128;
    const int bn = blockIdx.x * 128;
    const int tid = threadIdx.x;
    const int wid = tid >> 5;
    const int lane = tid & 31;
    const int wy = wid >> 1;
    const int wx = wid & 1;

    const uint32_t lmo = (uint32_t)((lane & 15) * PITCH + (lane >> 4) * 8);

    const int lr  = tid >> 2;            // 0..63 -> rows lr, lr+64 via it
    const int lsg = (tid & 3) * 8;       // elem offset in row

    float acc[2][8][4];
#pragma unroll
    for (int a = 0; a < 2; a++)
#pragma unroll
        for (int b = 0; b < 8; b++)
#pragma unroll
            for (int c = 0; c < 4; c++) acc[a][b][c] = 0.f;

    auto issue = [&](int kc, int stg) {
        const int k0 = kc * 32;
        const uint32_t sb = aBase + (uint32_t)(stg * GSTG) * 2;
#pragma unroll
        for (int it = 0; it < 2; it++) {
            const int r = lr + it * 64;
            const size_t gA = (size_t)(bm + r) * DM + k0 + lsg;
            const size_t gB = (size_t)(bn + r) * DM + k0 + lsg;
            const uint32_t so = (uint32_t)(r * PITCH + lsg) * 2;
            cp16(sb + so,                    Ahi + gA);
            cp16(sb + 5120 * 2 + so,         Alo + gA);
            cp16(sb + 10240 * 2 + so,        Bhi + gB);
            cp16(sb + 15360 * 2 + so,        Blo + gB);
        }
    };

    issue(0, 0);
    CP_COMMIT();

    for (int kc = 0; kc < 32; kc++) {
        const int cur = kc & 1;
        if (kc + 1 < 32) {
            issue(kc + 1, (kc + 1) & 1);
            CP_COMMIT();
            CP_WAIT1();
        } else {
            CP_WAIT0();
        }
        __syncthreads();

        const uint32_t sb = aBase + (uint32_t)(cur * GSTG) * 2;
        const uint32_t aAhi = sb;
        const uint32_t aAlo = sb + 5120 * 2;
        const uint32_t aBhi = sb + 10240 * 2;
        const uint32_t aBlo = sb + 15360 * 2;

#pragma unroll
        for (int ks = 0; ks < 2; ks++) {
            uint32_t ahi[2][4], alo[2][4], bhi[4][4], blo[4][4];
#pragma unroll
            for (int mt = 0; mt < 2; mt++) {
                const uint32_t org = (uint32_t)((wy * 32 + mt * 16) * PITCH + ks * 16);
                ldm_x4(aAhi + (org + lmo) * 2, ahi[mt]);
                ldm_x4(aAlo + (org + lmo) * 2, alo[mt]);
            }
#pragma unroll
            for (int np = 0; np < 4; np++) {
                const uint32_t org = (uint32_t)((wx * 64 + np * 16) * PITCH + ks * 16);
                ldm_x4(aBhi + (org + lmo) * 2, bhi[np]);
                ldm_x4(aBlo + (org + lmo) * 2, blo[np]);
            }
#pragma unroll
            for (int mt = 0; mt < 2; mt++) {
#pragma unroll
                for (int np = 0; np < 4; np++) {
                    mma_bf16(acc[mt][np * 2 + 0], ahi[mt], bhi[np][0], bhi[np][2]);
                    mma_bf16(acc[mt][np * 2 + 1], ahi[mt], bhi[np][1], bhi[np][3]);
                    mma_bf16(acc[mt][np * 2 + 0], alo[mt], bhi[np][0], bhi[np][2]);
                    mma_bf16(acc[mt][np * 2 + 1], alo[mt], bhi[np][1], bhi[np][3]);
                    mma_bf16(acc[mt][np * 2 + 0], ahi[mt], blo[np][0], blo[np][2]);
                    mma_bf16(acc[mt][np * 2 + 1], ahi[mt], blo[np][1], blo[np][3]);
                }
            }
        }
        __syncthreads();
    }

    // epilogue
    const int g   = lane >> 2;
    const int tig = lane & 3;
#pragma unroll
    for (int mt = 0; mt < 2; mt++) {
        const int row0 = bm + wy * 32 + mt * 16 + g;
#pragma unroll
        for (int nf = 0; nf < 8; nf++) {
            const int col = bn + wx * 64 + nf * 8 + tig * 2;
            const float* ac = acc[mt][nf];
            const float bx = bias[col], by = bias[col + 1];
            if (mode < 3) {
                __nv_bfloat16* __restrict__ ohi = (mode == 0) ? g_qhi : (mode == 1) ? g_khi : g_vhi;
                __nv_bfloat16* __restrict__ olo = (mode == 0) ? g_qlo : (mode == 1) ? g_klo : g_vlo;
                const int h = col >> 6, dh = col & 63;
#pragma unroll
                for (int rr = 0; rr < 2; rr++) {
                    const int row = row0 + rr * 8;
                    const int b = row >> 11, s = row & 2047;
                    const float vx = (ac[rr * 2 + 0] + bx) * oscale;
                    const float vy = (ac[rr * 2 + 1] + by) * oscale;
                    const size_t o = (((size_t)(b * NH + h)) * SEQ + s) * HD + dh;
                    *(uint32_t*)&ohi[o] = pkbf(vx, vy);
                    *(uint32_t*)&olo[o] = pkbf(vx - rbf(vx), vy - rbf(vy));
                }
            } else {
#pragma unroll
                for (int rr = 0; rr < 2; rr++) {
                    const int row = row0 + rr * 8;
                    float2 v = make_float2(ac[rr * 2 + 0] + bx, ac[rr * 2 + 1] + by);
                    *(float2*)&finalOut[(size_t)row * DM + col] = v;
                }
            }
        }
    }
}

// =============================================================================
// Flash attention, split bf16, Q-tile 128 x KV-tile 64, cp.async pipeline.
// No running max; exp2 via MUFU; deferred l-reduction; 2 CTAs/SM enforced.
// =============================================================================
#define APITCH 72
#define AQ_ELEMS (128 * APITCH)          // 9216
#define ASTG     (4 * 64 * APITCH)       // 18432 elems per KV stage
#define ATT_SMEM_BYTES ((2 * AQ_ELEMS + 2 * ASTG) * 2)   // 110592

__global__ __launch_bounds__(256, 2) void k_attn()
{
    extern __shared__ __nv_bfloat16 smb[];
    const uint32_t aBase = (uint32_t)__cvta_generic_to_shared(smb);
    const uint32_t aQhi = aBase;
    const uint32_t aQlo = aBase + AQ_ELEMS * 2;

    const int bh  = blockIdx.y;
    const int qt  = (int)gridDim.x - 1 - (int)blockIdx.x;  // heavy first
    const int tid = threadIdx.x;
    const int wid = tid >> 5;
    const int lane = tid & 31;
    const int g   = lane >> 2;
    const int q2  = lane & 3;

    const __nv_bfloat16* __restrict__ Qhi = g_qhi + (size_t)bh * SEQ * HD;
    const __nv_bfloat16* __restrict__ Qlo = g_qlo + (size_t)bh * SEQ * HD;
    const __nv_bfloat16* __restrict__ Khi = g_khi + (size_t)bh * SEQ * HD;
    const __nv_bfloat16* __restrict__ Klo = g_klo + (size_t)bh * SEQ * HD;
    const __nv_bfloat16* __restrict__ Vhi = g_vhi + (size_t)bh * SEQ * HD;
    const __nv_bfloat16* __restrict__ Vlo = g_vlo + (size_t)bh * SEQ * HD;

    // load Q tile (128 x 64) via cp.async
#pragma unroll
    for (int it = 0; it < 4; it++) {
        const int idx = it * 256 + tid;
        const int r  = idx >> 3;
        const int c8 = (idx & 7) * 8;
        const size_t gsrc = (size_t)(qt * 128 + r) * HD + c8;
        const uint32_t so = (uint32_t)(r * APITCH + c8) * 2;
        cp16(aQhi + so, Qhi + gsrc);
        cp16(aQlo + so, Qlo + gsrc);
    }

    const uint32_t lmo = (uint32_t)((lane & 15) * APITCH + (lane >> 4) * 8);
    const int lr  = tid >> 3;            // 0..31 (rows lr, lr+32)
    const int lc8 = (tid & 7) * 8;

    auto issueKV = [&](int kb, int stg) {
        const uint32_t sb = aBase + (uint32_t)(2 * AQ_ELEMS + stg * ASTG) * 2;
#pragma unroll
        for (int it = 0; it < 2; it++) {
            const int r = lr + it * 32;
            const size_t gsrc = (size_t)(kb * 64 + r) * HD + lc8;
            const uint32_t so = (uint32_t)(r * APITCH + lc8) * 2;
            cp16(sb + so,                      Khi + gsrc);
            cp16(sb + (64 * APITCH) * 2 + so,  Klo + gsrc);
            cp16(sb + (128 * APITCH) * 2 + so, Vhi + gsrc);
            cp16(sb + (192 * APITCH) * 2 + so, Vlo + gsrc);
        }
    };

    issueKV(0, 0);
    CP_COMMIT();

    float o[8][4];
#pragma unroll
    for (int j = 0; j < 8; j++)
#pragma unroll
        for (int c = 0; c < 4; c++) o[j][c] = 0.f;
    float l0 = 0.f, l1 = 0.f;   // per-thread partial sums (reduced at end)

    const int row0 = qt * 128 + wid * 16 + g;
    const int row1 = row0 + 8;
    const int wrow_max = qt * 128 + wid * 16 + 15;   // warp's max Q row
    const int nkb = 2 * qt + 2;

    for (int kb = 0; kb < nkb; kb++) {
        if (kb + 1 < nkb) {
            issueKV(kb + 1, (kb + 1) & 1);
            CP_COMMIT();
            CP_WAIT1();
        } else {
            CP_WAIT0();
        }
        __syncthreads();

        // fully-masked warp-block: no contribution (p would be all zero)
        if (kb * 64 > wrow_max) { __syncthreads(); continue; }

        const uint32_t sb = aBase + (uint32_t)(2 * AQ_ELEMS + (kb & 1) * ASTG) * 2;
        const uint32_t aKhi = sb;
        const uint32_t aKlo = sb + (64 * APITCH) * 2;
        const uint32_t aVhi = sb + (128 * APITCH) * 2;
        const uint32_t aVlo = sb + (192 * APITCH) * 2;

        // ---- S' = Q' K^T (3-pass split); Q' pre-scaled by log2e/32 ----
        float sf[8][4];
#pragma unroll
        for (int j = 0; j < 8; j++)
#pragma unroll
            for (int c = 0; c < 4; c++) sf[j][c] = 0.f;

#pragma unroll
        for (int kc = 0; kc < 4; kc++) {
            uint32_t qh[4], ql[4];
            const uint32_t orgA = (uint32_t)((wid * 16) * APITCH + kc * 16);
            ldm_x4(aQhi + (orgA + lmo) * 2, qh);
            ldm_x4(aQlo + (orgA + lmo) * 2, ql);
#pragma unroll
            for (int np = 0; np < 4; np++) {
                uint32_t kh[4], kl[4];
                const uint32_t orgB = (uint32_t)((np * 16) * APITCH + kc * 16);
                ldm_x4(aKhi + (orgB + lmo) * 2, kh);
                ldm_x4(aKlo + (orgB + lmo) * 2, kl);
                mma_bf16(sf[np * 2 + 0], qh, kh[0], kh[2]);
                mma_bf16(sf[np * 2 + 1], qh, kh[1], kh[3]);
                mma_bf16(sf[np * 2 + 0], ql, kh[0], kh[2]);
                mma_bf16(sf[np * 2 + 1], ql, kh[1], kh[3]);
                mma_bf16(sf[np * 2 + 0], qh, kl[0], kl[2]);
                mma_bf16(sf[np * 2 + 1], qh, kl[1], kl[3]);
            }
        }

        // ---- mask + exp2 + partial sums (no running max needed) ----
#pragma unroll
        for (int j = 0; j < 8; j++) {
            const int col = kb * 64 + j * 8 + q2 * 2;
            sf[j][0] = (col     > row0) ? 0.f : ex2(sf[j][0]);
            sf[j][1] = (col + 1 > row0) ? 0.f : ex2(sf[j][1]);
            sf[j][2] = (col     > row1) ? 0.f : ex2(sf[j][2]);
            sf[j][3] = (col + 1 > row1) ? 0.f : ex2(sf[j][3]);
            l0 += sf[j][0] + sf[j][1];
            l1 += sf[j][2] + sf[j][3];
        }

        // pack P -> split bf16 A fragments (ALU bit-trick for lo)
        uint32_t pah[4][4], pal[4][4];
#pragma unroll
        for (int kc = 0; kc < 4; kc++) {
            const int j0 = kc * 2, j1 = kc * 2 + 1;
            float f0 = sf[j0][0], f1 = sf[j0][1], f2 = sf[j0][2], f3 = sf[j0][3];
            float g0 = sf[j1][0], g1 = sf[j1][1], g2 = sf[j1][2], g3 = sf[j1][3];
            pah[kc][0] = pkbf(f0, f1);
            pah[kc][1] = pkbf(f2, f3);
            pah[kc][2] = pkbf(g0, g1);
            pah[kc][3] = pkbf(g2, g3);
            pal[kc][0] = pkbf(f0 - rbf(f0), f1 - rbf(f1));
            pal[kc][1] = pkbf(f2 - rbf(f2), f3 - rbf(f3));
            pal[kc][2] = pkbf(g0 - rbf(g0), g1 - rbf(g1));
            pal[kc][3] = pkbf(g2 - rbf(g2), g3 - rbf(g3));
        }

        // ---- O += P V (3-pass split) ----
#pragma unroll
        for (int kc = 0; kc < 4; kc++) {
#pragma unroll
            for (int np = 0; np < 4; np++) {
                uint32_t vh[4], vl[4];
                const uint32_t org = (uint32_t)((kc * 16) * APITCH + np * 16);
                ldm_x4_t(aVhi + (org + lmo) * 2, vh);
                ldm_x4_t(aVlo + (org + lmo) * 2, vl);
                mma_bf16(o[np * 2 + 0], pah[kc], vh[0], vh[1]);
                mma_bf16(o[np * 2 + 1], pah[kc], vh[2], vh[3]);
                mma_bf16(o[np * 2 + 0], pal[kc], vh[0], vh[1]);
                mma_bf16(o[np * 2 + 1], pal[kc], vh[2], vh[3]);
                mma_bf16(o[np * 2 + 0], pah[kc], vl[0], vl[1]);
                mma_bf16(o[np * 2 + 1], pah[kc], vl[2], vl[3]);
            }
        }
        __syncthreads();   // all reads of stage done before refill
    }

    // ---- deferred l reduction across the quad (2 shfl total) ----
    l0 += __shfl_xor_sync(0xffffffff, l0, 1);
    l0 += __shfl_xor_sync(0xffffffff, l0, 2);
    l1 += __shfl_xor_sync(0xffffffff, l1, 1);
    l1 += __shfl_xor_sync(0xffffffff, l1, 2);

    // ---- epilogue: normalize + write ctx split bf16 ----
    const float inv0 = 1.0f / l0;
    const float inv1 = 1.0f / l1;
    const int b = bh >> 4, h = bh & 15;
    const int s0 = qt * 128 + wid * 16 + g;
#pragma unroll
    for (int j = 0; j < 8; j++) {
        const int d = j * 8 + q2 * 2;
        {
            const float vx = o[j][0] * inv0, vy = o[j][1] * inv0;
            const size_t off = ((size_t)(b * SEQ + s0)) * DM + h * HD + d;
            *(uint32_t*)&g_chi[off] = pkbf(vx, vy);
            *(uint32_t*)&g_clo[off] = pkbf(vx - rbf(vx), vy - rbf(vy));
        }
        {
            const float vx = o[j][2] * inv1, vy = o[j][3] * inv1;
            const size_t off = ((size_t)(b * SEQ + s0 + 8)) * DM + h * HD + d;
            *(uint32_t*)&g_chi[off] = pkbf(vx, vy);
            *(uint32_t*)&g_clo[off] = pkbf(vx - rbf(vx), vy - rbf(vy));
        }
    }
}

// =============================================================================
extern "C" void kernel_launch(void* const* d_in, const int* in_sizes, int n_in,
                              void* d_out, int out_size)
{
    (void)in_sizes; (void)n_in; (void)out_size;
    const float* x  = (const float*)d_in[0];
    const float* Wq = (const float*)d_in[1];
    const float* bq = (const float*)d_in[2];
    const float* Wk = (const float*)d_in[3];
    const float* bk = (const float*)d_in[4];
    const float* Wv = (const float*)d_in[5];
    const float* bv = (const float*)d_in[6];
    const float* Wo = (const float*)d_in[7];
    const float* bo = (const float*)d_in[8];
    float* out = (float*)d_out;

    cudaFuncSetAttribute(k_gemm, cudaFuncAttributeMaxDynamicSharedMemorySize,
                         GEMM_SMEM_BYTES);
    cudaFuncSetAttribute(k_attn, cudaFuncAttributeMaxDynamicSharedMemorySize,
                         ATT_SMEM_BYTES);

    // 1) weight transpose + split, input split
    k_wT<<<dim3(32, 32, 4), 256>>>(Wq, Wk, Wv, Wo);
    k_split<<<(MROWS * DM) / 1024, 256>>>(x);

    // 2) QKV projections (mma.sync + cp.async pipeline); Q pre-scaled
    k_gemm<<<dim3(DM / 128, MROWS / 128, 3), 256, GEMM_SMEM_BYTES>>>(bq, bk, bv, nullptr, 0);

    // 3) flash attention (no-max softmax, MUFU exp2, 2 CTAs/SM)
    k_attn<<<dim3(SEQ / 128, NBH), 256, ATT_SMEM_BYTES>>>();

    // 4) output projection
    k_gemm<<<dim3(DM / 128, MROWS / 128, 1), 256, GEMM_SMEM_BYTES>>>(bo, bo, bo, out, 3);
}

// round 10
// speedup vs baseline: 1.7106x; 1.6588x over previous
#include <cuda_runtime.h>
#include <cuda_fp16.h>
#include <math.h>
#include <stdint.h>

#define BATCH 4
#define SEQ   2048
#define DM    1024
#define NH    16
#define HD    64
#define MROWS (BATCH*SEQ)      // 8192
#define NBH   (BATCH*NH)       // 64

// Q pre-scale folded into projection: log2(e) / sqrt(D_MODEL)
#define QSCALE 0.04508422002598762f   // 1.4426950408889634 / 32

// ---------------- scratch (device globals: allocation-free rule) -------------
__device__ __half g_xhi[(size_t)MROWS * DM];
__device__ __half g_xlo[(size_t)MROWS * DM];
__device__ __half g_chi[(size_t)MROWS * DM];     // ctx split
__device__ __half g_clo[(size_t)MROWS * DM];
__device__ __half g_wThi[(size_t)4 * DM * DM];   // W^T [n][k]
__device__ __half g_wTlo[(size_t)4 * DM * DM];
__device__ __half g_qhi[(size_t)NBH * SEQ * HD]; // [bh][s][64], pre-scaled
__device__ __half g_khi[(size_t)NBH * SEQ * HD];
__device__ __half g_vhi[(size_t)NBH * SEQ * HD];
__device__ __half g_vlo[(size_t)NBH * SEQ * HD];

// ======================= asm helpers =========================================
__device__ __forceinline__ void ldm_x4(uint32_t addr, uint32_t* r) {
    asm volatile("ldmatrix.sync.aligned.m8n8.x4.shared.b16 {%0,%1,%2,%3}, [%4];"
                 : "=r"(r[0]), "=r"(r[1]), "=r"(r[2]), "=r"(r[3]) : "r"(addr));
}
__device__ __forceinline__ void ldm_x4_t(uint32_t addr, uint32_t* r) {
    asm volatile("ldmatrix.sync.aligned.m8n8.x4.trans.shared.b16 {%0,%1,%2,%3}, [%4];"
                 : "=r"(r[0]), "=r"(r[1]), "=r"(r[2]), "=r"(r[3]) : "r"(addr));
}
__device__ __forceinline__ void mma_f16(float* c, const uint32_t* a,
                                        uint32_t b0, uint32_t b1) {
    asm volatile(
        "mma.sync.aligned.m16n8k16.row.col.f32.f16.f16.f32 "
        "{%0,%1,%2,%3}, {%4,%5,%6,%7}, {%8,%9}, {%0,%1,%2,%3};"
        : "+f"(c[0]), "+f"(c[1]), "+f"(c[2]), "+f"(c[3])
        : "r"(a[0]), "r"(a[1]), "r"(a[2]), "r"(a[3]), "r"(b0), "r"(b1));
}
__device__ __forceinline__ uint32_t pkh(float x, float y) {
    __half2 t = __floats2half2_rn(x, y);
    return *(uint32_t*)&t;
}
__device__ __forceinline__ float hlo(float x) {   // residual after fp16 RNE
    return x - __half2float(__float2half_rn(x));
}
// single-MUFU exp2
__device__ __forceinline__ float ex2(float x) {
    float y;
    asm("ex2.approx.f32 %0, %1;" : "=f"(y) : "f"(x));
    return y;
}
__device__ __forceinline__ void cp16(uint32_t dst, const void* src) {
    asm volatile("cp.async.cg.shared.global [%0], [%1], 16;"
                 :: "r"(dst), "l"(src) : "memory");
}
#define CP_COMMIT() asm volatile("cp.async.commit_group;" ::: "memory")
#define CP_WAIT1()  asm volatile("cp.async.wait_group 1;" ::: "memory")
#define CP_WAIT0()  asm volatile("cp.async.wait_group 0;" ::: "memory")

// =============================================================================
// split fp32 x -> hi/lo fp16
// =============================================================================
__global__ __launch_bounds__(256) void k_split(const float* __restrict__ x)
{
    const size_t i = ((size_t)blockIdx.x * 256 + threadIdx.x) * 4;
    float4 v = *(const float4*)(x + i);
    float vv[4] = {v.x, v.y, v.z, v.w};
    __half h[4], l[4];
#pragma unroll
    for (int u = 0; u < 4; u++) {
        h[u] = __float2half_rn(vv[u]);
        l[u] = __float2half_rn(vv[u] - __half2float(h[u]));
    }
    *(uint2*)(g_xhi + i) = *(uint2*)h;
    *(uint2*)(g_xlo + i) = *(uint2*)l;
}

// =============================================================================
// transpose + split weights: W [k][n] fp32 -> WT hi/lo [n][k] fp16
// =============================================================================
__global__ __launch_bounds__(256) void k_wT(
    const float* __restrict__ Wq, const float* __restrict__ Wk,
    const float* __restrict__ Wv, const float* __restrict__ Wo)
{
    const int z = blockIdx.z;
    const float* __restrict__ W = (z == 0) ? Wq : (z == 1) ? Wk : (z == 2) ? Wv : Wo;
    __half* __restrict__ Th = g_wThi + (size_t)z * DM * DM;
    __half* __restrict__ Tl = g_wTlo + (size_t)z * DM * DM;

    __shared__ float t[32][33];
    const int bk = blockIdx.y * 32, bn = blockIdx.x * 32;
    const int tx = threadIdx.x & 31, ty = threadIdx.x >> 5;

#pragma unroll
    for (int i = 0; i < 4; i++)
        t[ty + i * 8][tx] = W[(size_t)(bk + ty + i * 8) * DM + bn + tx];
    __syncthreads();
#pragma unroll
    for (int i = 0; i < 4; i++) {
        const float v = t[tx][ty + i * 8];
        const __half h = __float2half_rn(v);
        const size_t o = (size_t)(bn + ty + i * 8) * DM + bk + tx;
        Th[o] = h;
        Tl[o] = __float2half_rn(v - __half2float(h));
    }
}

// =============================================================================
// mma.sync fp16-split GEMM, 128x128 block, BK=32, cp.async 2-stage pipeline.
// npass per mode: Q,K = 1 (pure fp16), V,out = 2 (hi*Bhi + lo*Bhi).
// mode 0 (Q): output pre-scaled by QSCALE.
// =============================================================================
#define PITCH 40
#define GSTG  (3 * 128 * PITCH)                  // elems per stage = 15360
#define GEMM_SMEM_BYTES (2 * GSTG * 2)           // 61440

__global__ __launch_bounds__(256, 2) void k_gemm(
    const float* __restrict__ b0p, const float* __restrict__ b1p,
    const float* __restrict__ b2p, float* __restrict__ finalOut, int modeBase)
{
    extern __shared__ __half smg[];
    const uint32_t aBase = (uint32_t)__cvta_generic_to_shared(smg);

    const int z = blockIdx.z;
    const int mode = modeBase + z;
    const __half* __restrict__ Ahi = (mode < 3) ? g_xhi : g_chi;
    const __half* __restrict__ Alo = (mode < 3) ? g_xlo : g_clo;
    const int wsel = (mode < 3) ? z : 3;
    const __half* __restrict__ Bhi = g_wThi + (size_t)wsel * DM * DM;
    const float* __restrict__ bias = (mode == 0) ? b0p : (mode == 1) ? b1p
                                    : (mode == 2) ? b2p : b0p;
    const float oscale = (mode == 0) ? QSCALE : 1.0f;
    const int npass = (mode == 0 || mode == 1) ? 1 : 2;

    const int bm = blockIdx.y * 128;
    const int bn = blockIdx.x * 128;
    const int tid = threadIdx.x;
    const int wid = tid >> 5;
    const int lane = tid & 31;
    const int wy = wid >> 1;
    const int wx = wid & 1;

    const uint32_t lmo = (uint32_t)((lane & 15) * PITCH + (lane >> 4) * 8);

    const int lr  = tid >> 2;            // 0..63 -> rows lr, lr+64 via it
    const int lsg = (tid & 3) * 8;       // elem offset in row

    float acc[2][8][4];
#pragma unroll
    for (int a = 0; a < 2; a++)
#pragma unroll
        for (int b = 0; b < 8; b++)
#pragma unroll
            for (int c = 0; c < 4; c++) acc[a][b][c] = 0.f;

    auto issue = [&](int kc, int stg) {
        const int k0 = kc * 32;
        const uint32_t sb = aBase + (uint32_t)(stg * GSTG) * 2;
#pragma unroll
        for (int it = 0; it < 2; it++) {
            const int r = lr + it * 64;
            const size_t gA = (size_t)(bm + r) * DM + k0 + lsg;
            const size_t gB = (size_t)(bn + r) * DM + k0 + lsg;
            const uint32_t so = (uint32_t)(r * PITCH + lsg) * 2;
            cp16(sb + so,             Ahi + gA);
            if (npass >= 2) cp16(sb + 5120 * 2 + so, Alo + gA);
            cp16(sb + 10240 * 2 + so, Bhi + gB);
        }
    };

    issue(0, 0);
    CP_COMMIT();

    for (int kc = 0; kc < 32; kc++) {
        const int cur = kc & 1;
        if (kc + 1 < 32) {
            issue(kc + 1, (kc + 1) & 1);
            CP_COMMIT();
            CP_WAIT1();
        } else {
            CP_WAIT0();
        }
        __syncthreads();

        const uint32_t sb = aBase + (uint32_t)(cur * GSTG) * 2;
        const uint32_t aAhi = sb;
        const uint32_t aAlo = sb + 5120 * 2;
        const uint32_t aBhi = sb + 10240 * 2;

#pragma unroll
        for (int ks = 0; ks < 2; ks++) {
            uint32_t ahi[2][4], alo[2][4], bhi[4][4];
#pragma unroll
            for (int mt = 0; mt < 2; mt++) {
                const uint32_t org = (uint32_t)((wy * 32 + mt * 16) * PITCH + ks * 16);
                ldm_x4(aAhi + (org + lmo) * 2, ahi[mt]);
                if (npass >= 2) ldm_x4(aAlo + (org + lmo) * 2, alo[mt]);
            }
#pragma unroll
            for (int np = 0; np < 4; np++) {
                const uint32_t org = (uint32_t)((wx * 64 + np * 16) * PITCH + ks * 16);
                ldm_x4(aBhi + (org + lmo) * 2, bhi[np]);
            }
#pragma unroll
            for (int mt = 0; mt < 2; mt++) {
#pragma unroll
                for (int np = 0; np < 4; np++) {
                    mma_f16(acc[mt][np * 2 + 0], ahi[mt], bhi[np][0], bhi[np][2]);
                    mma_f16(acc[mt][np * 2 + 1], ahi[mt], bhi[np][1], bhi[np][3]);
                    if (npass >= 2) {
                        mma_f16(acc[mt][np * 2 + 0], alo[mt], bhi[np][0], bhi[np][2]);
                        mma_f16(acc[mt][np * 2 + 1], alo[mt], bhi[np][1], bhi[np][3]);
                    }
                }
            }
        }
        __syncthreads();
    }

    // epilogue
    const int g   = lane >> 2;
    const int tig = lane & 3;
#pragma unroll
    for (int mt = 0; mt < 2; mt++) {
        const int row0 = bm + wy * 32 + mt * 16 + g;
#pragma unroll
        for (int nf = 0; nf < 8; nf++) {
            const int col = bn + wx * 64 + nf * 8 + tig * 2;
            const float* ac = acc[mt][nf];
            const float bx = bias[col], by = bias[col + 1];
            if (mode < 3) {
                __half* __restrict__ ohi = (mode == 0) ? g_qhi : (mode == 1) ? g_khi : g_vhi;
                const int h = col >> 6, dh = col & 63;
#pragma unroll
                for (int rr = 0; rr < 2; rr++) {
                    const int row = row0 + rr * 8;
                    const int b = row >> 11, s = row & 2047;
                    const float vx = (ac[rr * 2 + 0] + bx) * oscale;
                    const float vy = (ac[rr * 2 + 1] + by) * oscale;
                    const size_t o = (((size_t)(b * NH + h)) * SEQ + s) * HD + dh;
                    *(uint32_t*)&ohi[o] = pkh(vx, vy);
                    if (mode == 2)
                        *(uint32_t*)&g_vlo[o] = pkh(hlo(vx), hlo(vy));
                }
            } else {
#pragma unroll
                for (int rr = 0; rr < 2; rr++) {
                    const int row = row0 + rr * 8;
                    float2 v = make_float2(ac[rr * 2 + 0] + bx, ac[rr * 2 + 1] + by);
                    *(float2*)&finalOut[(size_t)row * DM + col] = v;
                }
            }
        }
    }
}

// =============================================================================
// Flash attention, fp16, Q-tile 128 x KV-tile 64, cp.async pipeline.
// S: 1-pass fp16.  P@V: 2-pass (P*Vhi + P*Vlo).  No running max; MUFU exp2.
// =============================================================================
#define APITCH 72
#define AQ_ELEMS (128 * APITCH)          // 9216
#define ASTG     (3 * 64 * APITCH)       // 13824 elems per KV stage (Khi,Vhi,Vlo)
#define ATT_SMEM_BYTES ((AQ_ELEMS + 2 * ASTG) * 2)   // 73728

__global__ __launch_bounds__(256, 2) void k_attn()
{
    extern __shared__ __half smb[];
    const uint32_t aBase = (uint32_t)__cvta_generic_to_shared(smb);
    const uint32_t aQhi = aBase;

    const int bh  = blockIdx.y;
    const int qt  = (int)gridDim.x - 1 - (int)blockIdx.x;  // heavy first
    const int tid = threadIdx.x;
    const int wid = tid >> 5;
    const int lane = tid & 31;
    const int g   = lane >> 2;
    const int q2  = lane & 3;

    const __half* __restrict__ Qhi = g_qhi + (size_t)bh * SEQ * HD;
    const __half* __restrict__ Khi = g_khi + (size_t)bh * SEQ * HD;
    const __half* __restrict__ Vhi = g_vhi + (size_t)bh * SEQ * HD;
    const __half* __restrict__ Vlo = g_vlo + (size_t)bh * SEQ * HD;

    // load Q tile (128 x 64) via cp.async
#pragma unroll
    for (int it = 0; it < 4; it++) {
        const int idx = it * 256 + tid;
        const int r  = idx >> 3;
        const int c8 = (idx & 7) * 8;
        const size_t gsrc = (size_t)(qt * 128 + r) * HD + c8;
        cp16(aQhi + (uint32_t)(r * APITCH + c8) * 2, Qhi + gsrc);
    }

    const uint32_t lmo = (uint32_t)((lane & 15) * APITCH + (lane >> 4) * 8);
    const int lr  = tid >> 3;            // 0..31 (rows lr, lr+32)
    const int lc8 = (tid & 7) * 8;

    auto issueKV = [&](int kb, int stg) {
        const uint32_t sb = aBase + (uint32_t)(AQ_ELEMS + stg * ASTG) * 2;
#pragma unroll
        for (int it = 0; it < 2; it++) {
            const int r = lr + it * 32;
            const size_t gsrc = (size_t)(kb * 64 + r) * HD + lc8;
            const uint32_t so = (uint32_t)(r * APITCH + lc8) * 2;
            cp16(sb + so,                      Khi + gsrc);
            cp16(sb + (64 * APITCH) * 2 + so,  Vhi + gsrc);
            cp16(sb + (128 * APITCH) * 2 + so, Vlo + gsrc);
        }
    };

    issueKV(0, 0);
    CP_COMMIT();

    float o[8][4];
#pragma unroll
    for (int j = 0; j < 8; j++)
#pragma unroll
        for (int c = 0; c < 4; c++) o[j][c] = 0.f;
    float l0 = 0.f, l1 = 0.f;

    const int row0 = qt * 128 + wid * 16 + g;
    const int row1 = row0 + 8;
    const int wrow_max = qt * 128 + wid * 16 + 15;
    const int nkb = 2 * qt + 2;

    for (int kb = 0; kb < nkb; kb++) {
        if (kb + 1 < nkb) {
            issueKV(kb + 1, (kb + 1) & 1);
            CP_COMMIT();
            CP_WAIT1();
        } else {
            CP_WAIT0();
        }
        __syncthreads();

        // fully-masked warp-block: no contribution
        if (kb * 64 > wrow_max) { __syncthreads(); continue; }

        const uint32_t sb = aBase + (uint32_t)(AQ_ELEMS + (kb & 1) * ASTG) * 2;
        const uint32_t aKhi = sb;
        const uint32_t aVhi = sb + (64 * APITCH) * 2;
        const uint32_t aVlo = sb + (128 * APITCH) * 2;

        // ---- S' = Q' K^T (1-pass fp16); Q' pre-scaled by log2e/32 ----
        float sf[8][4];
#pragma unroll
        for (int j = 0; j < 8; j++)
#pragma unroll
            for (int c = 0; c < 4; c++) sf[j][c] = 0.f;

#pragma unroll
        for (int kc = 0; kc < 4; kc++) {
            uint32_t qh[4];
            const uint32_t orgA = (uint32_t)((wid * 16) * APITCH + kc * 16);
            ldm_x4(aQhi + (orgA + lmo) * 2, qh);
#pragma unroll
            for (int np = 0; np < 4; np++) {
                uint32_t kh[4];
                const uint32_t orgB = (uint32_t)((np * 16) * APITCH + kc * 16);
                ldm_x4(aKhi + (orgB + lmo) * 2, kh);
                mma_f16(sf[np * 2 + 0], qh, kh[0], kh[2]);
                mma_f16(sf[np * 2 + 1], qh, kh[1], kh[3]);
            }
        }

        // ---- mask + exp2 + partial sums ----
#pragma unroll
        for (int j = 0; j < 8; j++) {
            const int col = kb * 64 + j * 8 + q2 * 2;
            sf[j][0] = (col     > row0) ? 0.f : ex2(sf[j][0]);
            sf[j][1] = (col + 1 > row0) ? 0.f : ex2(sf[j][1]);
            sf[j][2] = (col     > row1) ? 0.f : ex2(sf[j][2]);
            sf[j][3] = (col + 1 > row1) ? 0.f : ex2(sf[j][3]);
            l0 += sf[j][0] + sf[j][1];
            l1 += sf[j][2] + sf[j][3];
        }

        // pack P -> fp16 A fragments (single precision level)
        uint32_t pah[4][4];
#pragma unroll
        for (int kc = 0; kc < 4; kc++) {
            const int j0 = kc * 2, j1 = kc * 2 + 1;
            pah[kc][0] = pkh(sf[j0][0], sf[j0][1]);
            pah[kc][1] = pkh(sf[j0][2], sf[j0][3]);
            pah[kc][2] = pkh(sf[j1][0], sf[j1][1]);
            pah[kc][3] = pkh(sf[j1][2], sf[j1][3]);
        }

        // ---- O += P (Vhi + Vlo) (2-pass) ----
#pragma unroll
        for (int kc = 0; kc < 4; kc++) {
#pragma unroll
            for (int np = 0; np < 4; np++) {
                uint32_t vh[4], vl[4];
                const uint32_t org = (uint32_t)((kc * 16) * APITCH + np * 16);
                ldm_x4_t(aVhi + (org + lmo) * 2, vh);
                ldm_x4_t(aVlo + (org + lmo) * 2, vl);
                mma_f16(o[np * 2 + 0], pah[kc], vh[0], vh[1]);
                mma_f16(o[np * 2 + 1], pah[kc], vh[2], vh[3]);
                mma_f16(o[np * 2 + 0], pah[kc], vl[0], vl[1]);
                mma_f16(o[np * 2 + 1], pah[kc], vl[2], vl[3]);
            }
        }
        __syncthreads();   // all reads of stage done before refill
    }

    // ---- deferred l reduction across the quad ----
    l0 += __shfl_xor_sync(0xffffffff, l0, 1);
    l0 += __shfl_xor_sync(0xffffffff, l0, 2);
    l1 += __shfl_xor_sync(0xffffffff, l1, 1);
    l1 += __shfl_xor_sync(0xffffffff, l1, 2);

    // ---- epilogue: normalize + write ctx split fp16 ----
    const float inv0 = 1.0f / l0;
    const float inv1 = 1.0f / l1;
    const int b = bh >> 4, h = bh & 15;
    const int s0 = qt * 128 + wid * 16 + g;
#pragma unroll
    for (int j = 0; j < 8; j++) {
        const int d = j * 8 + q2 * 2;
        {
            const float vx = o[j][0] * inv0, vy = o[j][1] * inv0;
            const size_t off = ((size_t)(b * SEQ + s0)) * DM + h * HD + d;
            *(uint32_t*)&g_chi[off] = pkh(vx, vy);
            *(uint32_t*)&g_clo[off] = pkh(hlo(vx), hlo(vy));
        }
        {
            const float vx = o[j][2] * inv1, vy = o[j][3] * inv1;
            const size_t off = ((size_t)(b * SEQ + s0 + 8)) * DM + h * HD + d;
            *(uint32_t*)&g_chi[off] = pkh(vx, vy);
            *(uint32_t*)&g_clo[off] = pkh(hlo(vx), hlo(vy));
        }
    }
}

// =============================================================================
extern "C" void kernel_launch(void* const* d_in, const int* in_sizes, int n_in,
                              void* d_out, int out_size)
{
    (void)in_sizes; (void)n_in; (void)out_size;
    const float* x  = (const float*)d_in[0];
    const float* Wq = (const float*)d_in[1];
    const float* bq = (const float*)d_in[2];
    const float* Wk = (const float*)d_in[3];
    const float* bk = (const float*)d_in[4];
    const float* Wv = (const float*)d_in[5];
    const float* bv = (const float*)d_in[6];
    const float* Wo = (const float*)d_in[7];
    const float* bo = (const float*)d_in[8];
    float* out = (float*)d_out;

    cudaFuncSetAttribute(k_gemm, cudaFuncAttributeMaxDynamicSharedMemorySize,
                         GEMM_SMEM_BYTES);
    cudaFuncSetAttribute(k_attn, cudaFuncAttributeMaxDynamicSharedMemorySize,
                         ATT_SMEM_BYTES);

    // 1) weight transpose + split, input split
    k_wT<<<dim3(32, 32, 4), 256>>>(Wq, Wk, Wv, Wo);
    k_split<<<(MROWS * DM) / 1024, 256>>>(x);

    // 2) QKV projections (fp16 mma; Q,K 1-pass, V 2-pass); Q pre-scaled
    k_gemm<<<dim3(DM / 128, MROWS / 128, 3), 256, GEMM_SMEM_BYTES>>>(bq, bk, bv, nullptr, 0);

    // 3) flash attention (fp16, 1-pass S, 2-pass PV)
    k_attn<<<dim3(SEQ / 128, NBH), 256, ATT_SMEM_BYTES>>>();

    // 4) output projection (fp16 2-pass)
    k_gemm<<<dim3(DM / 128, MROWS / 128, 1), 256, GEMM_SMEM_BYTES>>>(bo, bo, bo, out, 3);
}

// round 11
// speedup vs baseline: 1.9458x; 1.1375x over previous
#include <cuda_runtime.h>
#include <cuda_fp16.h>
#include <math.h>
#include <stdint.h>

#define BATCH 4
#define SEQ   2048
#define DM    1024
#define NH    16
#define HD    64
#define MROWS (BATCH*SEQ)      // 8192
#define NBH   (BATCH*NH)       // 64

// Q pre-scale folded into projection: log2(e) / sqrt(D_MODEL)
#define QSCALE 0.04508422002598762f   // 1.4426950408889634 / 32

// ---------------- scratch (device globals: allocation-free rule) -------------
__device__ __half g_xhi[(size_t)MROWS * DM];
__device__ __half g_xlo[(size_t)MROWS * DM];
__device__ __half g_chi[(size_t)MROWS * DM];     // ctx split (out-proj stays 2-pass)
__device__ __half g_clo[(size_t)MROWS * DM];
__device__ __half g_wThi[(size_t)4 * DM * DM];   // W^T [n][k]
__device__ __half g_qhi[(size_t)NBH * SEQ * HD]; // [bh][s][64], pre-scaled
__device__ __half g_khi[(size_t)NBH * SEQ * HD];
__device__ __half g_vhi[(size_t)NBH * SEQ * HD];

// ======================= asm helpers =========================================
__device__ __forceinline__ void ldm_x4(uint32_t addr, uint32_t* r) {
    asm volatile("ldmatrix.sync.aligned.m8n8.x4.shared.b16 {%0,%1,%2,%3}, [%4];"
                 : "=r"(r[0]), "=r"(r[1]), "=r"(r[2]), "=r"(r[3]) : "r"(addr));
}
__device__ __forceinline__ void ldm_x4_t(uint32_t addr, uint32_t* r) {
    asm volatile("ldmatrix.sync.aligned.m8n8.x4.trans.shared.b16 {%0,%1,%2,%3}, [%4];"
                 : "=r"(r[0]), "=r"(r[1]), "=r"(r[2]), "=r"(r[3]) : "r"(addr));
}
__device__ __forceinline__ void mma_f16(float* c, const uint32_t* a,
                                        uint32_t b0, uint32_t b1) {
    asm volatile(
        "mma.sync.aligned.m16n8k16.row.col.f32.f16.f16.f32 "
        "{%0,%1,%2,%3}, {%4,%5,%6,%7}, {%8,%9}, {%0,%1,%2,%3};"
        : "+f"(c[0]), "+f"(c[1]), "+f"(c[2]), "+f"(c[3])
        : "r"(a[0]), "r"(a[1]), "r"(a[2]), "r"(a[3]), "r"(b0), "r"(b1));
}
__device__ __forceinline__ uint32_t pkh(float x, float y) {
    __half2 t = __floats2half2_rn(x, y);
    return *(uint32_t*)&t;
}
__device__ __forceinline__ float hlo(float x) {   // residual after fp16 RNE
    return x - __half2float(__float2half_rn(x));
}
// single-MUFU exp2
__device__ __forceinline__ float ex2(float x) {
    float y;
    asm("ex2.approx.f32 %0, %1;" : "=f"(y) : "f"(x));
    return y;
}
__device__ __forceinline__ void cp16(uint32_t dst, const void* src) {
    asm volatile("cp.async.cg.shared.global [%0], [%1], 16;"
                 :: "r"(dst), "l"(src) : "memory");
}
#define CP_COMMIT() asm volatile("cp.async.commit_group;" ::: "memory")
#define CP_WAIT1()  asm volatile("cp.async.wait_group 1;" ::: "memory")
#define CP_WAIT0()  asm volatile("cp.async.wait_group 0;" ::: "memory")

// =============================================================================
// split fp32 x -> hi/lo fp16
// =============================================================================
__global__ __launch_bounds__(256) void k_split(const float* __restrict__ x)
{
    const size_t i = ((size_t)blockIdx.x * 256 + threadIdx.x) * 4;
    float4 v = *(const float4*)(x + i);
    float vv[4] = {v.x, v.y, v.z, v.w};
    __half h[4], l[4];
#pragma unroll
    for (int u = 0; u < 4; u++) {
        h[u] = __float2half_rn(vv[u]);
        l[u] = __float2half_rn(vv[u] - __half2float(h[u]));
    }
    *(uint2*)(g_xhi + i) = *(uint2*)h;
    *(uint2*)(g_xlo + i) = *(uint2*)l;
}

// =============================================================================
// transpose weights: W [k][n] fp32 -> WT hi [n][k] fp16
// =============================================================================
__global__ __launch_bounds__(256) void k_wT(
    const float* __restrict__ Wq, const float* __restrict__ Wk,
    const float* __restrict__ Wv, const float* __restrict__ Wo)
{
    const int z = blockIdx.z;
    const float* __restrict__ W = (z == 0) ? Wq : (z == 1) ? Wk : (z == 2) ? Wv : Wo;
    __half* __restrict__ Th = g_wThi + (size_t)z * DM * DM;

    __shared__ float t[32][33];
    const int bk = blockIdx.y * 32, bn = blockIdx.x * 32;
    const int tx = threadIdx.x & 31, ty = threadIdx.x >> 5;

#pragma unroll
    for (int i = 0; i < 4; i++)
        t[ty + i * 8][tx] = W[(size_t)(bk + ty + i * 8) * DM + bn + tx];
    __syncthreads();
#pragma unroll
    for (int i = 0; i < 4; i++) {
        const float v = t[tx][ty + i * 8];
        Th[(size_t)(bn + ty + i * 8) * DM + bk + tx] = __float2half_rn(v);
    }
}

// =============================================================================
// mma.sync fp16 GEMM, 128x128 block, BK=32, cp.async 2-stage pipeline.
// npass: Q,K,V = 1 (pure fp16); out = 2 (ctx_hi*W + ctx_lo*W).
// mode 0 (Q): output pre-scaled by QSCALE.
// =============================================================================
#define PITCH 40
#define GSTG  (3 * 128 * PITCH)                  // elems per stage = 15360
#define GEMM_SMEM_BYTES (2 * GSTG * 2)           // 61440

__global__ __launch_bounds__(256, 2) void k_gemm(
    const float* __restrict__ b0p, const float* __restrict__ b1p,
    const float* __restrict__ b2p, float* __restrict__ finalOut, int modeBase)
{
    extern __shared__ __half smg[];
    const uint32_t aBase = (uint32_t)__cvta_generic_to_shared(smg);

    const int z = blockIdx.z;
    const int mode = modeBase + z;
    const __half* __restrict__ Ahi = (mode < 3) ? g_xhi : g_chi;
    const __half* __restrict__ Alo = (mode < 3) ? g_xlo : g_clo;
    const int wsel = (mode < 3) ? z : 3;
    const __half* __restrict__ Bhi = g_wThi + (size_t)wsel * DM * DM;
    const float* __restrict__ bias = (mode == 0) ? b0p : (mode == 1) ? b1p
                                    : (mode == 2) ? b2p : b0p;
    const float oscale = (mode == 0) ? QSCALE : 1.0f;
    const int npass = (mode == 3) ? 2 : 1;

    const int bm = blockIdx.y * 128;
    const int bn = blockIdx.x * 128;
    const int tid = threadIdx.x;
    const int wid = tid >> 5;
    const int lane = tid & 31;
    const int wy = wid >> 1;
    const int wx = wid & 1;

    const uint32_t lmo = (uint32_t)((lane & 15) * PITCH + (lane >> 4) * 8);

    const int lr  = tid >> 2;            // 0..63 -> rows lr, lr+64 via it
    const int lsg = (tid & 3) * 8;       // elem offset in row

    float acc[2][8][4];
#pragma unroll
    for (int a = 0; a < 2; a++)
#pragma unroll
        for (int b = 0; b < 8; b++)
#pragma unroll
            for (int c = 0; c < 4; c++) acc[a][b][c] = 0.f;

    auto issue = [&](int kc, int stg) {
        const int k0 = kc * 32;
        const uint32_t sb = aBase + (uint32_t)(stg * GSTG) * 2;
#pragma unroll
        for (int it = 0; it < 2; it++) {
            const int r = lr + it * 64;
            const size_t gA = (size_t)(bm + r) * DM + k0 + lsg;
            const size_t gB = (size_t)(bn + r) * DM + k0 + lsg;
            const uint32_t so = (uint32_t)(r * PITCH + lsg) * 2;
            cp16(sb + so,             Ahi + gA);
            if (npass >= 2) cp16(sb + 5120 * 2 + so, Alo + gA);
            cp16(sb + 10240 * 2 + so, Bhi + gB);
        }
    };

    issue(0, 0);
    CP_COMMIT();

    for (int kc = 0; kc < 32; kc++) {
        const int cur = kc & 1;
        if (kc + 1 < 32) {
            issue(kc + 1, (kc + 1) & 1);
            CP_COMMIT();
            CP_WAIT1();
        } else {
            CP_WAIT0();
        }
        __syncthreads();

        const uint32_t sb = aBase + (uint32_t)(cur * GSTG) * 2;
        const uint32_t aAhi = sb;
        const uint32_t aAlo = sb + 5120 * 2;
        const uint32_t aBhi = sb + 10240 * 2;

#pragma unroll
        for (int ks = 0; ks < 2; ks++) {
            uint32_t ahi[2][4], alo[2][4], bhi[4][4];
#pragma unroll
            for (int mt = 0; mt < 2; mt++) {
                const uint32_t org = (uint32_t)((wy * 32 + mt * 16) * PITCH + ks * 16);
                ldm_x4(aAhi + (org + lmo) * 2, ahi[mt]);
                if (npass >= 2) ldm_x4(aAlo + (org + lmo) * 2, alo[mt]);
            }
#pragma unroll
            for (int np = 0; np < 4; np++) {
                const uint32_t org = (uint32_t)((wx * 64 + np * 16) * PITCH + ks * 16);
                ldm_x4(aBhi + (org + lmo) * 2, bhi[np]);
            }
#pragma unroll
            for (int mt = 0; mt < 2; mt++) {
#pragma unroll
                for (int np = 0; np < 4; np++) {
                    mma_f16(acc[mt][np * 2 + 0], ahi[mt], bhi[np][0], bhi[np][2]);
                    mma_f16(acc[mt][np * 2 + 1], ahi[mt], bhi[np][1], bhi[np][3]);
                    if (npass >= 2) {
                        mma_f16(acc[mt][np * 2 + 0], alo[mt], bhi[np][0], bhi[np][2]);
                        mma_f16(acc[mt][np * 2 + 1], alo[mt], bhi[np][1], bhi[np][3]);
                    }
                }
            }
        }
        __syncthreads();
    }

    // epilogue
    const int g   = lane >> 2;
    const int tig = lane & 3;
#pragma unroll
    for (int mt = 0; mt < 2; mt++) {
        const int row0 = bm + wy * 32 + mt * 16 + g;
#pragma unroll
        for (int nf = 0; nf < 8; nf++) {
            const int col = bn + wx * 64 + nf * 8 + tig * 2;
            const float* ac = acc[mt][nf];
            const float bx = bias[col], by = bias[col + 1];
            if (mode < 3) {
                __half* __restrict__ ohi = (mode == 0) ? g_qhi : (mode == 1) ? g_khi : g_vhi;
                const int h = col >> 6, dh = col & 63;
#pragma unroll
                for (int rr = 0; rr < 2; rr++) {
                    const int row = row0 + rr * 8;
                    const int b = row >> 11, s = row & 2047;
                    const float vx = (ac[rr * 2 + 0] + bx) * oscale;
                    const float vy = (ac[rr * 2 + 1] + by) * oscale;
                    const size_t o = (((size_t)(b * NH + h)) * SEQ + s) * HD + dh;
                    *(uint32_t*)&ohi[o] = pkh(vx, vy);
                }
            } else {
#pragma unroll
                for (int rr = 0; rr < 2; rr++) {
                    const int row = row0 + rr * 8;
                    float2 v = make_float2(ac[rr * 2 + 0] + bx, ac[rr * 2 + 1] + by);
                    *(float2*)&finalOut[(size_t)row * DM + col] = v;
                }
            }
        }
    }
}

// =============================================================================
// Flash attention, fp16, Q-tile 128 x KV-tile 64, cp.async pipeline.
// S: 1-pass.  P@V: 1-pass.  No running max; MUFU exp2; mask only on diagonal.
// =============================================================================
#define APITCH 72
#define AQ_ELEMS (128 * APITCH)          // 9216
#define ASTG     (2 * 64 * APITCH)       // 9216 elems per KV stage (Khi,Vhi)
#define ATT_SMEM_BYTES ((AQ_ELEMS + 2 * ASTG) * 2)   // 55296

__global__ __launch_bounds__(256, 2) void k_attn()
{
    extern __shared__ __half smb[];
    const uint32_t aBase = (uint32_t)__cvta_generic_to_shared(smb);
    const uint32_t aQhi = aBase;

    const int bh  = blockIdx.y;
    const int qt  = (int)gridDim.x - 1 - (int)blockIdx.x;  // heavy first
    const int tid = threadIdx.x;
    const int wid = tid >> 5;
    const int lane = tid & 31;
    const int g   = lane >> 2;
    const int q2  = lane & 3;

    const __half* __restrict__ Qhi = g_qhi + (size_t)bh * SEQ * HD;
    const __half* __restrict__ Khi = g_khi + (size_t)bh * SEQ * HD;
    const __half* __restrict__ Vhi = g_vhi + (size_t)bh * SEQ * HD;

    // load Q tile (128 x 64) via cp.async
#pragma unroll
    for (int it = 0; it < 4; it++) {
        const int idx = it * 256 + tid;
        const int r  = idx >> 3;
        const int c8 = (idx & 7) * 8;
        const size_t gsrc = (size_t)(qt * 128 + r) * HD + c8;
        cp16(aQhi + (uint32_t)(r * APITCH + c8) * 2, Qhi + gsrc);
    }

    const uint32_t lmo = (uint32_t)((lane & 15) * APITCH + (lane >> 4) * 8);
    const int lr  = tid >> 3;            // 0..31 (rows lr, lr+32)
    const int lc8 = (tid & 7) * 8;

    auto issueKV = [&](int kb, int stg) {
        const uint32_t sb = aBase + (uint32_t)(AQ_ELEMS + stg * ASTG) * 2;
#pragma unroll
        for (int it = 0; it < 2; it++) {
            const int r = lr + it * 32;
            const size_t gsrc = (size_t)(kb * 64 + r) * HD + lc8;
            const uint32_t so = (uint32_t)(r * APITCH + lc8) * 2;
            cp16(sb + so,                     Khi + gsrc);
            cp16(sb + (64 * APITCH) * 2 + so, Vhi + gsrc);
        }
    };

    issueKV(0, 0);
    CP_COMMIT();

    float o[8][4];
#pragma unroll
    for (int j = 0; j < 8; j++)
#pragma unroll
        for (int c = 0; c < 4; c++) o[j][c] = 0.f;
    float l0 = 0.f, l1 = 0.f;

    const int row0 = qt * 128 + wid * 16 + g;
    const int row1 = row0 + 8;
    const int wrow_min = qt * 128 + wid * 16;        // warp's min Q row
    const int wrow_max = wrow_min + 15;              // warp's max Q row
    const int nkb = 2 * qt + 2;

    for (int kb = 0; kb < nkb; kb++) {
        if (kb + 1 < nkb) {
            issueKV(kb + 1, (kb + 1) & 1);
            CP_COMMIT();
            CP_WAIT1();
        } else {
            CP_WAIT0();
        }
        __syncthreads();

        // fully-masked warp-block: no contribution
        if (kb * 64 > wrow_max) { __syncthreads(); continue; }

        const uint32_t sb = aBase + (uint32_t)(AQ_ELEMS + (kb & 1) * ASTG) * 2;
        const uint32_t aKhi = sb;
        const uint32_t aVhi = sb + (64 * APITCH) * 2;

        // ---- S' = Q' K^T (1-pass fp16); Q' pre-scaled by log2e/32 ----
        float sf[8][4];
#pragma unroll
        for (int j = 0; j < 8; j++)
#pragma unroll
            for (int c = 0; c < 4; c++) sf[j][c] = 0.f;

#pragma unroll
        for (int kc = 0; kc < 4; kc++) {
            uint32_t qh[4];
            const uint32_t orgA = (uint32_t)((wid * 16) * APITCH + kc * 16);
            ldm_x4(aQhi + (orgA + lmo) * 2, qh);
#pragma unroll
            for (int np = 0; np < 4; np++) {
                uint32_t kh[4];
                const uint32_t orgB = (uint32_t)((np * 16) * APITCH + kc * 16);
                ldm_x4(aKhi + (orgB + lmo) * 2, kh);
                mma_f16(sf[np * 2 + 0], qh, kh[0], kh[2]);
                mma_f16(sf[np * 2 + 1], qh, kh[1], kh[3]);
            }
        }

        // ---- exp2 + partial sums; causal compares only near the diagonal ----
        if (kb * 64 + 63 <= wrow_min) {
            // whole KV block strictly below the warp's rows: no masking
#pragma unroll
            for (int j = 0; j < 8; j++) {
                sf[j][0] = ex2(sf[j][0]);
                sf[j][1] = ex2(sf[j][1]);
                sf[j][2] = ex2(sf[j][2]);
                sf[j][3] = ex2(sf[j][3]);
                l0 += sf[j][0] + sf[j][1];
                l1 += sf[j][2] + sf[j][3];
            }
        } else {
#pragma unroll
            for (int j = 0; j < 8; j++) {
                const int col = kb * 64 + j * 8 + q2 * 2;
                sf[j][0] = (col     > row0) ? 0.f : ex2(sf[j][0]);
                sf[j][1] = (col + 1 > row0) ? 0.f : ex2(sf[j][1]);
                sf[j][2] = (col     > row1) ? 0.f : ex2(sf[j][2]);
                sf[j][3] = (col + 1 > row1) ? 0.f : ex2(sf[j][3]);
                l0 += sf[j][0] + sf[j][1];
                l1 += sf[j][2] + sf[j][3];
            }
        }

        // pack P -> fp16 A fragments
        uint32_t pah[4][4];
#pragma unroll
        for (int kc = 0; kc < 4; kc++) {
            const int j0 = kc * 2, j1 = kc * 2 + 1;
            pah[kc][0] = pkh(sf[j0][0], sf[j0][1]);
            pah[kc][1] = pkh(sf[j0][2], sf[j0][3]);
            pah[kc][2] = pkh(sf[j1][0], sf[j1][1]);
            pah[kc][3] = pkh(sf[j1][2], sf[j1][3]);
        }

        // ---- O += P Vhi (1-pass) ----
#pragma unroll
        for (int kc = 0; kc < 4; kc++) {
#pragma unroll
            for (int np = 0; np < 4; np++) {
                uint32_t vh[4];
                const uint32_t org = (uint32_t)((kc * 16) * APITCH + np * 16);
                ldm_x4_t(aVhi + (org + lmo) * 2, vh);
                mma_f16(o[np * 2 + 0], pah[kc], vh[0], vh[1]);
                mma_f16(o[np * 2 + 1], pah[kc], vh[2], vh[3]);
            }
        }
        __syncthreads();   // all reads of stage done before refill
    }

    // ---- deferred l reduction across the quad ----
    l0 += __shfl_xor_sync(0xffffffff, l0, 1);
    l0 += __shfl_xor_sync(0xffffffff, l0, 2);
    l1 += __shfl_xor_sync(0xffffffff, l1, 1);
    l1 += __shfl_xor_sync(0xffffffff, l1, 2);

    // ---- epilogue: normalize + write ctx split fp16 ----
    const float inv0 = 1.0f / l0;
    const float inv1 = 1.0f / l1;
    const int b = bh >> 4, h = bh & 15;
    const int s0 = qt * 128 + wid * 16 + g;
#pragma unroll
    for (int j = 0; j < 8; j++) {
        const int d = j * 8 + q2 * 2;
        {
            const float vx = o[j][0] * inv0, vy = o[j][1] * inv0;
            const size_t off = ((size_t)(b * SEQ + s0)) * DM + h * HD + d;
            *(uint32_t*)&g_chi[off] = pkh(vx, vy);
            *(uint32_t*)&g_clo[off] = pkh(hlo(vx), hlo(vy));
        }
        {
            const float vx = o[j][2] * inv1, vy = o[j][3] * inv1;
            const size_t off = ((size_t)(b * SEQ + s0 + 8)) * DM + h * HD + d;
            *(uint32_t*)&g_chi[off] = pkh(vx, vy);
            *(uint32_t*)&g_clo[off] = pkh(hlo(vx), hlo(vy));
        }
    }
}

// =============================================================================
extern "C" void kernel_launch(void* const* d_in, const int* in_sizes, int n_in,
                              void* d_out, int out_size)
{
    (void)in_sizes; (void)n_in; (void)out_size;
    const float* x  = (const float*)d_in[0];
    const float* Wq = (const float*)d_in[1];
    const float* bq = (const float*)d_in[2];
    const float* Wk = (const float*)d_in[3];
    const float* bk = (const float*)d_in[4];
    const float* Wv = (const float*)d_in[5];
    const float* bv = (const float*)d_in[6];
    const float* Wo = (const float*)d_in[7];
    const float* bo = (const float*)d_in[8];
    float* out = (float*)d_out;

    cudaFuncSetAttribute(k_gemm, cudaFuncAttributeMaxDynamicSharedMemorySize,
                         GEMM_SMEM_BYTES);
    cudaFuncSetAttribute(k_attn, cudaFuncAttributeMaxDynamicSharedMemorySize,
                         ATT_SMEM_BYTES);

    // 1) weight transpose, input split
    k_wT<<<dim3(32, 32, 4), 256>>>(Wq, Wk, Wv, Wo);
    k_split<<<(MROWS * DM) / 1024, 256>>>(x);

    // 2) QKV projections (fp16 1-pass); Q pre-scaled
    k_gemm<<<dim3(DM / 128, MROWS / 128, 3), 256, GEMM_SMEM_BYTES>>>(bq, bk, bv, nullptr, 0);

    // 3) flash attention (fp16, 1-pass S, 1-pass PV)
    k_attn<<<dim3(SEQ / 128, NBH), 256, ATT_SMEM_BYTES>>>();

    // 4) output projection (fp16 2-pass: ctx hi/lo)
    k_gemm<<<dim3(DM / 128, MROWS / 128, 1), 256, GEMM_SMEM_BYTES>>>(bo, bo, bo, out, 3);
}